// round 1
// baseline (speedup 1.0000x reference)
#include <cuda_runtime.h>
#include <cstdint>

#define N_NODES   8192
#define THREADS   512
#define NBINS     256
#define CAND_MAX  2048
#define VEC_ITERS (N_NODES / 4 / THREADS)   // 4 float4 per thread
#define ELT_ITERS (N_NODES / THREADS)       // 16 elements per thread

// Monotonic float -> uint mapping (larger float => larger uint). No NaNs in inputs.
__device__ __forceinline__ uint32_t f2ord(float f) {
    uint32_t u = __float_as_uint(f);
    return u ^ ((uint32_t)((int32_t)u >> 31) | 0x80000000u);
}

// 48-bit total-order key: [ord:32 | 000 | (8191-j):13]. Unique per element; ties in
// value resolve to the smaller index (matching jax.lax.top_k).
__device__ __forceinline__ unsigned long long make_key(uint32_t ord, int j) {
    return ((unsigned long long)ord << 16) | (unsigned)(N_NODES - 1 - j);
}

// Warp-0-only: suffix-sum the 256-bin histogram and pick the bin containing the
// krem-th largest element. Updates prefix/krem; reports chosen-bin population.
__device__ __forceinline__ void scan_and_pick(volatile uint32_t* s_hist,
                                              volatile uint32_t* s_cum,
                                              unsigned long long* s_prefix,
                                              int* s_krem,
                                              uint32_t* s_binct)
{
    const int lane = threadIdx.x;           // caller guarantees tid < 32
    uint32_t h[8], suf[8];
    #pragma unroll
    for (int j = 0; j < 8; ++j) h[j] = s_hist[lane * 8 + j];
    uint32_t acc = 0;
    #pragma unroll
    for (int j = 7; j >= 0; --j) { acc += h[j]; suf[j] = acc; }
    // inclusive suffix-sum of per-lane totals across the warp
    uint32_t run = acc;
    #pragma unroll
    for (int off = 1; off < 32; off <<= 1) {
        uint32_t v = __shfl_down_sync(0xFFFFFFFFu, run, off);
        if (lane + off < 32) run += v;
    }
    const uint32_t above = run - acc;       // sum over lanes > lane
    #pragma unroll
    for (int j = 0; j < 8; ++j) s_cum[lane * 8 + j] = above + suf[j];
    if (lane == 0) s_cum[NBINS] = 0;
    __syncwarp();
    const uint32_t krem = (uint32_t)(*s_krem);
    #pragma unroll
    for (int j = 0; j < 8; ++j) {
        const int b = lane * 8 + j;
        const uint32_t ge = s_cum[b];       // count of digits >= b
        const uint32_t gt = s_cum[b + 1];   // count of digits >  b
        if (ge >= krem && gt < krem) {      // exactly one (lane,j) hits this
            *s_prefix = (*s_prefix << 8) | (unsigned long long)(uint32_t)b;
            *s_krem   = (int)(krem - gt);
            *s_binct  = ge - gt;
        }
    }
}

__global__ __launch_bounds__(THREADS, 4)
void st_subset_sampler_kernel(const float* __restrict__ scores,
                              const float* __restrict__ noise,
                              const float* __restrict__ tau_p,
                              const int*   __restrict__ k_p,
                              float* __restrict__ out)
{
    __shared__ uint32_t s_ord[N_NODES];          // 32 KB: ordered keys of g
    __shared__ uint32_t s_hist[NBINS];
    __shared__ uint32_t s_cum[NBINS + 1];
    __shared__ uint16_t s_cand[CAND_MAX];        // candidate indices after pass 0
    __shared__ int      s_ncand;
    __shared__ unsigned long long s_prefix;
    __shared__ int      s_krem;
    __shared__ uint32_t s_binct;

    const int tid = threadIdx.x;
    const size_t row_off = (size_t)blockIdx.x * N_NODES;
    const float tau = __ldg(tau_p);
    const int   k   = __ldg(k_p);

    const float4* sp = reinterpret_cast<const float4*>(scores + row_off);
    const float4* np = reinterpret_cast<const float4*>(noise  + row_off);

    // ---- load row, compute g = scores/tau + noise, store ordered keys to smem ----
    #pragma unroll
    for (int i = 0; i < VEC_ITERS; ++i) {
        const int idx = tid + i * THREADS;
        const float4 a = sp[idx];
        const float4 b = np[idx];
        uint4 o;
        o.x = f2ord(__fdiv_rn(a.x, tau) + b.x);
        o.y = f2ord(__fdiv_rn(a.y, tau) + b.y);
        o.z = f2ord(__fdiv_rn(a.z, tau) + b.z);
        o.w = f2ord(__fdiv_rn(a.w, tau) + b.w);
        reinterpret_cast<uint4*>(s_ord)[idx] = o;
    }
    if (tid == 0) { s_krem = k; s_prefix = 0ull; s_ncand = 0; }
    if (tid < NBINS) s_hist[tid] = 0;
    __syncthreads();

    // ---- radix pass 0: digit = top byte of ord, over all N elements ----
    // Exponent bytes cluster heavily, so aggregate equal digits within the warp
    // before the smem atomic to avoid same-address ATOMS serialization.
    #pragma unroll
    for (int i = 0; i < ELT_ITERS; ++i) {
        const uint32_t dig = s_ord[tid + i * THREADS] >> 24;
        const unsigned peers = __match_any_sync(0xFFFFFFFFu, dig);
        if ((threadIdx.x & 31) == (__ffs(peers) - 1))
            atomicAdd(&s_hist[dig], (uint32_t)__popc(peers));
    }
    __syncthreads();
    if (tid < 32) scan_and_pick(s_hist, s_cum, &s_prefix, &s_krem, &s_binct);
    __syncthreads();

    // ---- compact candidates (elements in the chosen top byte) ----
    const bool use_cand = (s_binct <= CAND_MAX);
    const uint32_t p0 = (uint32_t)s_prefix;
    if (use_cand) {
        #pragma unroll
        for (int i = 0; i < ELT_ITERS; ++i) {
            const int j = tid + i * THREADS;
            if ((s_ord[j] >> 24) == p0) {
                const int pos = atomicAdd(&s_ncand, 1);
                s_cand[pos] = (uint16_t)j;
            }
        }
    }
    __syncthreads();

    // ---- radix passes 1..5 over candidates (or all elements in the rare fat-bin case) ----
    for (int d = 1; d < 6; ++d) {
        if (tid < NBINS) s_hist[tid] = 0;
        __syncthreads();
        const int shift_dig = 40 - 8 * d;
        const int shift_pre = 48 - 8 * d;
        const unsigned long long pre = s_prefix;
        if (use_cand) {
            const int nc = s_ncand;
            for (int i = tid; i < nc; i += THREADS) {
                const int j = s_cand[i];
                const unsigned long long key = make_key(s_ord[j], j);
                if ((key >> shift_pre) == pre)
                    atomicAdd(&s_hist[(uint32_t)(key >> shift_dig) & 0xFFu], 1u);
            }
        } else {
            #pragma unroll
            for (int i = 0; i < ELT_ITERS; ++i) {
                const int j = tid + i * THREADS;
                const unsigned long long key = make_key(s_ord[j], j);
                if ((key >> shift_pre) == pre)
                    atomicAdd(&s_hist[(uint32_t)(key >> shift_dig) & 0xFFu], 1u);
            }
        }
        __syncthreads();
        if (tid < 32) scan_and_pick(s_hist, s_cum, &s_prefix, &s_krem, &s_binct);
        __syncthreads();
    }

    // ---- write k-hot row: exactly k elements have key >= threshold key ----
    const unsigned long long thr = s_prefix;
    float4* op = reinterpret_cast<float4*>(out + row_off);
    #pragma unroll
    for (int i = 0; i < VEC_ITERS; ++i) {
        const int idx = tid + i * THREADS;
        const uint4 o = reinterpret_cast<const uint4*>(s_ord)[idx];
        const int j = idx * 4;
        float4 r;
        r.x = (make_key(o.x, j + 0) >= thr) ? 1.0f : 0.0f;
        r.y = (make_key(o.y, j + 1) >= thr) ? 1.0f : 0.0f;
        r.z = (make_key(o.z, j + 2) >= thr) ? 1.0f : 0.0f;
        r.w = (make_key(o.w, j + 3) >= thr) ? 1.0f : 0.0f;
        op[idx] = r;
    }
}

extern "C" void kernel_launch(void* const* d_in, const int* in_sizes, int n_in,
                              void* d_out, int out_size) {
    (void)in_sizes; (void)n_in; (void)out_size;
    const float* scores = (const float*)d_in[0];
    const float* noise  = (const float*)d_in[1];
    const float* tau    = (const float*)d_in[2];
    const int*   k      = (const int*)d_in[3];
    float* out = (float*)d_out;
    st_subset_sampler_kernel<<<N_NODES, THREADS>>>(scores, noise, tau, k, out);
}

// round 2
// speedup vs baseline: 1.6108x; 1.6108x over previous
#include <cuda_runtime.h>
#include <cstdint>

#define N_NODES   8192
#define THREADS   512
#define NBINS     256
#define CAND_MAX  1024
#define VEC_ITERS (N_NODES / 4 / THREADS)   // 4 float4 per thread

// Monotonic float -> uint mapping (larger float => larger uint). No NaNs in inputs.
__device__ __forceinline__ uint32_t f2ord(float f) {
    uint32_t u = __float_as_uint(f);
    return u ^ ((uint32_t)((int32_t)u >> 31) | 0x80000000u);
}

// Warp-0-only: suffix-sum a 256-bin histogram and pick the bin containing the
// krem-th largest element. Shifts the bin into *s_prefix, updates krem, binct.
__device__ __forceinline__ void scan_pick(const uint32_t* hist,
                                          volatile uint32_t* s_cum,
                                          unsigned long long* s_prefix,
                                          int* s_krem,
                                          uint32_t* s_binct)
{
    const int lane = threadIdx.x;           // caller guarantees tid < 32
    uint32_t h[8], suf[8];
    #pragma unroll
    for (int j = 0; j < 8; ++j) h[j] = hist[lane * 8 + j];
    uint32_t acc = 0;
    #pragma unroll
    for (int j = 7; j >= 0; --j) { acc += h[j]; suf[j] = acc; }
    uint32_t run = acc;
    #pragma unroll
    for (int off = 1; off < 32; off <<= 1) {
        uint32_t v = __shfl_down_sync(0xFFFFFFFFu, run, off);
        if (lane + off < 32) run += v;
    }
    const uint32_t above = run - acc;       // sum over lanes > lane
    #pragma unroll
    for (int j = 0; j < 8; ++j) s_cum[lane * 8 + j] = above + suf[j];
    if (lane == 0) s_cum[NBINS] = 0;
    __syncwarp();
    const uint32_t krem = (uint32_t)(*s_krem);
    #pragma unroll
    for (int j = 0; j < 8; ++j) {
        const int b = lane * 8 + j;
        const uint32_t ge = s_cum[b];       // count >= b
        const uint32_t gt = s_cum[b + 1];   // count >  b
        if (ge >= krem && gt < krem) {      // exactly one (lane,j) hits
            *s_prefix = (*s_prefix << 8) | (unsigned long long)(uint32_t)b;
            *s_krem   = (int)(krem - gt);
            *s_binct  = ge - gt;
        }
    }
}

__global__ __launch_bounds__(THREADS, 4)
void st_subset_sampler_kernel(const float* __restrict__ scores,
                              const float* __restrict__ noise,
                              const float* __restrict__ tau_p,
                              const int*   __restrict__ k_p,
                              float* __restrict__ out)
{
    __shared__ uint32_t s_ord[N_NODES];          // 32 KB ordered keys
    __shared__ uint32_t s_hist[6][NBINS];        // 6 pre-zeroed histograms
    __shared__ uint32_t s_cum[NBINS + 1];
    __shared__ uint32_t s_cord[CAND_MAX];        // candidate ord values
    __shared__ uint16_t s_cidx[CAND_MAX];        // candidate column indices
    __shared__ int      s_ncand;
    __shared__ unsigned long long s_prefix;
    __shared__ int      s_krem;
    __shared__ uint32_t s_binct;
    __shared__ uint32_t s_jcut;

    const int tid = threadIdx.x;
    const size_t row = (size_t)blockIdx.x * N_NODES;
    const float tau = __ldg(tau_p);
    const int   k   = __ldg(k_p);

    // Power-of-two tau => a/tau == a*(1/tau) exactly; mul-then-add matches
    // the reference rounding bit-for-bit. Otherwise exact fdiv fallback.
    const uint32_t tb = __float_as_uint(tau);
    const bool pow2 = ((tb & 0x007FFFFFu) == 0u) &&
                      ((tb & 0x7F800000u) != 0u) &&
                      ((tb & 0x7F800000u) != 0x7F800000u);
    const float rtau = __frcp_rn(tau);           // exact for pow2 tau

    const float4* sp = reinterpret_cast<const float4*>(scores + row);
    const float4* np = reinterpret_cast<const float4*>(noise  + row);

    // ---- load: ord keys to smem, per-thread max of 16 in register ----
    uint32_t m = 0;
    if (pow2) {
        #pragma unroll
        for (int i = 0; i < VEC_ITERS; ++i) {
            const int idx = tid + i * THREADS;
            const float4 a = sp[idx];
            const float4 b = np[idx];
            uint4 o;
            o.x = f2ord(__fadd_rn(__fmul_rn(a.x, rtau), b.x));
            o.y = f2ord(__fadd_rn(__fmul_rn(a.y, rtau), b.y));
            o.z = f2ord(__fadd_rn(__fmul_rn(a.z, rtau), b.z));
            o.w = f2ord(__fadd_rn(__fmul_rn(a.w, rtau), b.w));
            reinterpret_cast<uint4*>(s_ord)[idx] = o;
            m = max(m, max(max(o.x, o.y), max(o.z, o.w)));
        }
    } else {
        #pragma unroll
        for (int i = 0; i < VEC_ITERS; ++i) {
            const int idx = tid + i * THREADS;
            const float4 a = sp[idx];
            const float4 b = np[idx];
            uint4 o;
            o.x = f2ord(__fadd_rn(__fdiv_rn(a.x, tau), b.x));
            o.y = f2ord(__fadd_rn(__fdiv_rn(a.y, tau), b.y));
            o.z = f2ord(__fadd_rn(__fdiv_rn(a.z, tau), b.z));
            o.w = f2ord(__fadd_rn(__fdiv_rn(a.w, tau), b.w));
            reinterpret_cast<uint4*>(s_ord)[idx] = o;
            m = max(m, max(max(o.x, o.y), max(o.z, o.w)));
        }
    }
    if (tid == 0) { s_ncand = 0; s_prefix = 0ull; s_krem = k; }
    #pragma unroll
    for (int i = 0; i < 3; ++i)                 // zero all 6 histograms
        (&s_hist[0][0])[tid + i * THREADS] = 0;
    __syncthreads();

    // ---- pass A over 512 per-thread maxima: top byte ----
    {
        const uint32_t dig = m >> 24;
        const unsigned peers = __match_any_sync(0xFFFFFFFFu, dig);
        if ((tid & 31) == (__ffs(peers) - 1))
            atomicAdd(&s_hist[0][dig], (uint32_t)__popc(peers));
    }
    __syncthreads();
    if (tid < 32) scan_pick(s_hist[0], s_cum, &s_prefix, &s_krem, &s_binct);
    __syncthreads();

    // ---- pass B over maxima: second byte within chosen top byte ----
    {
        const uint32_t pb = (uint32_t)s_prefix;
        const bool part = ((m >> 24) == pb);
        const uint32_t dig = part ? ((m >> 16) & 0xFFu) : 0x100u;
        const unsigned peers = __match_any_sync(0xFFFFFFFFu, dig);
        if (part && (tid & 31) == (__ffs(peers) - 1))
            atomicAdd(&s_hist[1][dig & 0xFFu], (uint32_t)__popc(peers));
    }
    __syncthreads();
    if (tid < 32) scan_pick(s_hist[1], s_cum, &s_prefix, &s_krem, &s_binct);
    __syncthreads();

    // t32 <= m_k <= true threshold T  (k-th largest of maxima bounds v_k)
    const uint32_t t32 = ((uint32_t)s_prefix) << 16;

    // ---- fused provisional write + candidate compaction ----
    float4* op = reinterpret_cast<float4*>(out + row);
    #pragma unroll
    for (int i = 0; i < VEC_ITERS; ++i) {
        const int idx = tid + i * THREADS;
        const uint4 o = reinterpret_cast<const uint4*>(s_ord)[idx];
        float4 r;
        r.x = (o.x >= t32) ? 1.0f : 0.0f;
        r.y = (o.y >= t32) ? 1.0f : 0.0f;
        r.z = (o.z >= t32) ? 1.0f : 0.0f;
        r.w = (o.w >= t32) ? 1.0f : 0.0f;
        op[idx] = r;
        const int j = idx * 4;
        if (o.x >= t32) { int p = atomicAdd(&s_ncand, 1); if (p < CAND_MAX) { s_cord[p] = o.x; s_cidx[p] = (uint16_t)(j + 0); } }
        if (o.y >= t32) { int p = atomicAdd(&s_ncand, 1); if (p < CAND_MAX) { s_cord[p] = o.y; s_cidx[p] = (uint16_t)(j + 1); } }
        if (o.z >= t32) { int p = atomicAdd(&s_ncand, 1); if (p < CAND_MAX) { s_cord[p] = o.z; s_cidx[p] = (uint16_t)(j + 2); } }
        if (o.w >= t32) { int p = atomicAdd(&s_ncand, 1); if (p < CAND_MAX) { s_cord[p] = o.w; s_cidx[p] = (uint16_t)(j + 3); } }
    }
    __syncthreads();
    const int nc = s_ncand;
    if (tid == 0) { s_prefix = 0ull; s_krem = k; }   // reset for exact select

    if (nc <= CAND_MAX) {
        // ---- exact 32-bit threshold over candidates: 4 radix passes ----
        #pragma unroll
        for (int d = 0; d < 4; ++d) {
            __syncthreads();                         // prefix stable, hist clean
            const uint32_t pre = (uint32_t)s_prefix;
            const int sh = 24 - 8 * d;
            for (int i = tid; i < nc; i += THREADS) {
                const uint32_t o = s_cord[i];
                const bool part = (d == 0) || ((o >> (sh + 8)) == pre);
                if (part) atomicAdd(&s_hist[2 + d][(o >> sh) & 0xFFu], 1u);
            }
            __syncthreads();
            if (tid < 32) scan_pick(s_hist[2 + d], s_cum, &s_prefix, &s_krem, &s_binct);
        }
        __syncthreads();
        const uint32_t thr = (uint32_t)s_prefix;     // exact k-th largest value
        const int rem = s_krem;                      // ties to include (>=1)

        // ---- tie-break: rem-th smallest index among ord==thr (warp 0) ----
        if (tid < 32) {
            uint32_t jcut = 0, last = 0;
            for (int it = 0; it < rem; ++it) {
                uint32_t cur = 0xFFFFFFFFu;
                for (int base = 0; base < nc; base += 32) {
                    const int i = base + tid;
                    if (i < nc && s_cord[i] == thr && (uint32_t)s_cidx[i] >= last)
                        cur = min(cur, (uint32_t)s_cidx[i]);
                }
                cur = __reduce_min_sync(0xFFFFFFFFu, cur);
                jcut = cur; last = cur + 1;
            }
            if (tid == 0) s_jcut = jcut;
        }
        __syncthreads();

        // ---- fixup: rewrite every candidate with its exact 0/1 ----
        const uint32_t jc = s_jcut;
        for (int i = tid; i < nc; i += THREADS) {
            const uint32_t o = s_cord[i];
            const uint32_t j = s_cidx[i];
            out[row + j] = (o > thr || (o == thr && j <= jc)) ? 1.0f : 0.0f;
        }
    } else {
        // ---- fallback (never on random data): exact 48-bit full radix ----
        for (int d = 0; d < 6; ++d) {
            if (tid < NBINS) s_hist[0][tid] = 0;
            __syncthreads();
            const unsigned long long pre = s_prefix;
            const int shd = 40 - 8 * d, shp = 48 - 8 * d;
            for (int jj = tid; jj < N_NODES; jj += THREADS) {
                const unsigned long long key =
                    ((unsigned long long)s_ord[jj] << 16) | (unsigned)(N_NODES - 1 - jj);
                const bool part = (d == 0) || ((key >> shp) == pre);
                if (part) atomicAdd(&s_hist[0][(uint32_t)(key >> shd) & 0xFFu], 1u);
            }
            __syncthreads();
            if (tid < 32) scan_pick(s_hist[0], s_cum, &s_prefix, &s_krem, &s_binct);
            __syncthreads();
        }
        const unsigned long long thr = s_prefix;
        for (int jj = tid; jj < N_NODES; jj += THREADS) {
            const unsigned long long key =
                ((unsigned long long)s_ord[jj] << 16) | (unsigned)(N_NODES - 1 - jj);
            out[row + jj] = (key >= thr) ? 1.0f : 0.0f;
        }
    }
}

extern "C" void kernel_launch(void* const* d_in, const int* in_sizes, int n_in,
                              void* d_out, int out_size) {
    (void)in_sizes; (void)n_in; (void)out_size;
    const float* scores = (const float*)d_in[0];
    const float* noise  = (const float*)d_in[1];
    const float* tau    = (const float*)d_in[2];
    const int*   k      = (const int*)d_in[3];
    float* out = (float*)d_out;
    st_subset_sampler_kernel<<<N_NODES, THREADS>>>(scores, noise, tau, k, out);
}

// round 3
// speedup vs baseline: 2.0400x; 1.2664x over previous
#include <cuda_runtime.h>
#include <cstdint>

#define N_NODES   8192
#define THREADS   512
#define GRID      592              // persistent: fits one wave on 148+ SMs at 4 CTA/SM
#define NBINS     256
#define CAND_MAX  1024
#define NGROUPS   64               // 8-lane group maxima
#define VEC_ITERS (N_NODES / 4 / THREADS)   // 4 float4 per thread

// Monotonic float -> uint mapping (larger float => larger uint). No NaNs in inputs.
__device__ __forceinline__ uint32_t f2ord(float f) {
    uint32_t u = __float_as_uint(f);
    return u ^ ((uint32_t)((int32_t)u >> 31) | 0x80000000u);
}

// Unique 48-bit total-order key: ties in value resolve to the smaller index
// (matching jax.lax.top_k).
__device__ __forceinline__ unsigned long long make_key(uint32_t ord, uint32_t j) {
    return ((unsigned long long)ord << 16) | (unsigned)(N_NODES - 1 - j);
}

// Fallback-only: suffix-sum a 256-bin histogram, pick bin holding krem-th largest.
__device__ __forceinline__ void scan_pick(const uint32_t* hist,
                                          volatile uint32_t* s_cum,
                                          unsigned long long* s_prefix,
                                          int* s_krem)
{
    const int lane = threadIdx.x;           // caller guarantees tid < 32
    uint32_t h[8], suf[8];
    #pragma unroll
    for (int j = 0; j < 8; ++j) h[j] = hist[lane * 8 + j];
    uint32_t acc = 0;
    #pragma unroll
    for (int j = 7; j >= 0; --j) { acc += h[j]; suf[j] = acc; }
    uint32_t run = acc;
    #pragma unroll
    for (int off = 1; off < 32; off <<= 1) {
        uint32_t v = __shfl_down_sync(0xFFFFFFFFu, run, off);
        if (lane + off < 32) run += v;
    }
    const uint32_t above = run - acc;
    #pragma unroll
    for (int j = 0; j < 8; ++j) s_cum[lane * 8 + j] = above + suf[j];
    if (lane == 0) s_cum[NBINS] = 0;
    __syncwarp();
    const uint32_t krem = (uint32_t)(*s_krem);
    #pragma unroll
    for (int j = 0; j < 8; ++j) {
        const int b = lane * 8 + j;
        const uint32_t ge = s_cum[b];
        const uint32_t gt = s_cum[b + 1];
        if (ge >= krem && gt < krem) {
            *s_prefix = (*s_prefix << 8) | (unsigned long long)(uint32_t)b;
            *s_krem   = (int)(krem - gt);
        }
    }
}

__global__ __launch_bounds__(THREADS, 4)
void st_subset_sampler_kernel(const float* __restrict__ scores,
                              const float* __restrict__ noise,
                              const float* __restrict__ tau_p,
                              const int*   __restrict__ k_p,
                              float* __restrict__ out)
{
    __shared__ uint32_t s_ord[N_NODES];            // 32 KB ordered keys
    __shared__ uint32_t s_gmax[NGROUPS];           // 64 group maxima
    __shared__ unsigned long long s_ckey[CAND_MAX];// candidate keys (8 KB)
    __shared__ int      s_ncand;
    __shared__ uint32_t s_t32;
    // fallback-only state
    __shared__ uint32_t s_hist[NBINS];
    __shared__ uint32_t s_cum[NBINS + 1];
    __shared__ unsigned long long s_prefix;
    __shared__ int      s_krem;

    const int tid = threadIdx.x;
    const float tau = __ldg(tau_p);
    const int   k   = __ldg(k_p);

    // Power-of-two tau => a/tau == a*(1/tau) exactly; mul-then-add matches the
    // reference rounding bit-for-bit. Otherwise exact fdiv fallback.
    const uint32_t tb = __float_as_uint(tau);
    const bool pow2 = ((tb & 0x007FFFFFu) == 0u) &&
                      ((tb & 0x7F800000u) != 0u) &&
                      ((tb & 0x7F800000u) != 0x7F800000u);
    const float rtau = __frcp_rn(tau);

    for (int row_i = blockIdx.x; row_i < N_NODES; row_i += GRID) {
        const size_t row = (size_t)row_i * N_NODES;
        const float4* sp = reinterpret_cast<const float4*>(scores + row);
        const float4* np = reinterpret_cast<const float4*>(noise  + row);

        if (tid == 0) { s_ncand = 0; s_t32 = 0; }

        // ---- phase 1: load, compute ord -> smem, per-thread max ----
        uint32_t m = 0;
        if (pow2) {
            #pragma unroll
            for (int i = 0; i < VEC_ITERS; ++i) {
                const int idx = tid + i * THREADS;
                const float4 a = sp[idx];
                const float4 b = np[idx];
                uint4 o;
                o.x = f2ord(__fadd_rn(__fmul_rn(a.x, rtau), b.x));
                o.y = f2ord(__fadd_rn(__fmul_rn(a.y, rtau), b.y));
                o.z = f2ord(__fadd_rn(__fmul_rn(a.z, rtau), b.z));
                o.w = f2ord(__fadd_rn(__fmul_rn(a.w, rtau), b.w));
                reinterpret_cast<uint4*>(s_ord)[idx] = o;
                m = max(m, max(max(o.x, o.y), max(o.z, o.w)));
            }
        } else {
            #pragma unroll
            for (int i = 0; i < VEC_ITERS; ++i) {
                const int idx = tid + i * THREADS;
                const float4 a = sp[idx];
                const float4 b = np[idx];
                uint4 o;
                o.x = f2ord(__fadd_rn(__fdiv_rn(a.x, tau), b.x));
                o.y = f2ord(__fadd_rn(__fdiv_rn(a.y, tau), b.y));
                o.z = f2ord(__fadd_rn(__fdiv_rn(a.z, tau), b.z));
                o.w = f2ord(__fadd_rn(__fdiv_rn(a.w, tau), b.w));
                reinterpret_cast<uint4*>(s_ord)[idx] = o;
                m = max(m, max(max(o.x, o.y), max(o.z, o.w)));
            }
        }
        // 8-lane group max -> 64 group maxima
        #pragma unroll
        for (int off = 4; off > 0; off >>= 1)
            m = max(m, __shfl_down_sync(0xFFFFFFFFu, m, off, 8));
        if ((tid & 7) == 0) s_gmax[tid >> 3] = m;
        __syncthreads();

        // ---- phase 2: warp 0 exact-ranks the 64 group maxima ----
        // t32 = k-th largest group max <= true k-th largest element T
        // (the top-k group maxima are k distinct elements, each >= t32).
        if (tid < 32 && k >= 1 && k <= NGROUPS) {
            const uint32_t v0 = s_gmax[tid];
            const uint32_t v1 = s_gmax[tid + 32];
            int r0 = 0, r1 = 0;
            #pragma unroll 8
            for (int j = 0; j < NGROUPS; ++j) {
                const uint32_t w = s_gmax[j];
                r0 += (w > v0) || (w == v0 && j < tid);
                r1 += (w > v1) || (w == v1 && j < tid + 32);
            }
            if (r0 == k - 1) s_t32 = v0;
            if (r1 == k - 1) s_t32 = v1;
        }
        __syncthreads();
        const uint32_t t32 = s_t32;

        // ---- phase 3: fused provisional write + candidate compaction ----
        float4* op = reinterpret_cast<float4*>(out + row);
        #pragma unroll
        for (int i = 0; i < VEC_ITERS; ++i) {
            const int idx = tid + i * THREADS;
            const uint4 o = reinterpret_cast<const uint4*>(s_ord)[idx];
            float4 r;
            r.x = (o.x >= t32) ? 1.0f : 0.0f;
            r.y = (o.y >= t32) ? 1.0f : 0.0f;
            r.z = (o.z >= t32) ? 1.0f : 0.0f;
            r.w = (o.w >= t32) ? 1.0f : 0.0f;
            op[idx] = r;
            const uint32_t j = (uint32_t)idx * 4;
            if (o.x >= t32) { int p = atomicAdd(&s_ncand, 1); if (p < CAND_MAX) s_ckey[p] = make_key(o.x, j + 0); }
            if (o.y >= t32) { int p = atomicAdd(&s_ncand, 1); if (p < CAND_MAX) s_ckey[p] = make_key(o.y, j + 1); }
            if (o.z >= t32) { int p = atomicAdd(&s_ncand, 1); if (p < CAND_MAX) s_ckey[p] = make_key(o.z, j + 2); }
            if (o.w >= t32) { int p = atomicAdd(&s_ncand, 1); if (p < CAND_MAX) s_ckey[p] = make_key(o.w, j + 3); }
        }
        __syncthreads();
        const int nc = s_ncand;

        if (nc <= CAND_MAX) {
            // ---- phase 4: O(nc^2) exact rank over candidates (nc ~ k) ----
            // All true top-k have ord >= T >= t32, so they are candidates;
            // keys are unique, so (rank < k) selects exactly the global top-k.
            for (int c = tid; c < nc; c += THREADS) {
                const unsigned long long key = s_ckey[c];
                int rank = 0;
                for (int t = 0; t < nc; ++t)
                    rank += (s_ckey[t] > key);
                const uint32_t j = (uint32_t)(N_NODES - 1) - (uint32_t)(key & 0xFFFFu);
                out[row + j] = (rank < k) ? 1.0f : 0.0f;
            }
        } else {
            // ---- fallback (adversarial inputs only): exact 48-bit radix ----
            if (tid == 0) { s_prefix = 0ull; s_krem = k; }
            for (int d = 0; d < 6; ++d) {
                if (tid < NBINS) s_hist[tid] = 0;
                __syncthreads();
                const unsigned long long pre = s_prefix;
                const int shd = 40 - 8 * d, shp = 48 - 8 * d;
                for (int jj = tid; jj < N_NODES; jj += THREADS) {
                    const unsigned long long key = make_key(s_ord[jj], (uint32_t)jj);
                    if (d == 0 || (key >> shp) == pre)
                        atomicAdd(&s_hist[(uint32_t)(key >> shd) & 0xFFu], 1u);
                }
                __syncthreads();
                if (tid < 32) scan_pick(s_hist, s_cum, &s_prefix, &s_krem);
                __syncthreads();
            }
            const unsigned long long thr = s_prefix;
            for (int jj = tid; jj < N_NODES; jj += THREADS)
                out[row + jj] = (make_key(s_ord[jj], (uint32_t)jj) >= thr) ? 1.0f : 0.0f;
        }
        __syncthreads();   // protect s_ord / s_ckey / s_ncand reuse next row
    }
}

extern "C" void kernel_launch(void* const* d_in, const int* in_sizes, int n_in,
                              void* d_out, int out_size) {
    (void)in_sizes; (void)n_in; (void)out_size;
    const float* scores = (const float*)d_in[0];
    const float* noise  = (const float*)d_in[1];
    const float* tau    = (const float*)d_in[2];
    const int*   k      = (const int*)d_in[3];
    float* out = (float*)d_out;
    st_subset_sampler_kernel<<<GRID, THREADS>>>(scores, noise, tau, k, out);
}